// round 2
// baseline (speedup 1.0000x reference)
#include <cuda_runtime.h>
#include <cstdint>

static constexpr int BATCH   = 20000;
static constexpr int A_BYTES = 131072;          // 8 K-chunks x 128 rows x 128B (tf32 W tile)
static constexpr int B_ROWS  = 256;             // padded N rows per B buffer
static constexpr int B_BUF   = B_ROWS * 128;    // 32KB per buffer
static constexpr int SMEM_BYTES = A_BYTES + 2 * B_BUF;  // 196608

__device__ __forceinline__ uint32_t smem_u32(const void* p) {
    uint32_t a;
    asm("{ .reg .u64 t; cvta.to.shared.u64 t, %1; cvt.u32.u64 %0, t; }" : "=r"(a) : "l"(p));
    return a;
}
__device__ __forceinline__ uint32_t f2tf32(float f) {
    uint32_t u;
    asm("cvt.rna.tf32.f32 %0, %1;" : "=r"(u) : "f"(f));
    return u;
}
__device__ __forceinline__ uint32_t sw128(uint32_t o) { return o ^ ((o >> 3) & 0x70); }

__device__ __forceinline__ void ldsm4(uint32_t* r, uint32_t a) {
    asm volatile("ldmatrix.sync.aligned.m8n8.x4.shared.b16 {%0,%1,%2,%3}, [%4];"
                 : "=r"(r[0]), "=r"(r[1]), "=r"(r[2]), "=r"(r[3]) : "r"(a));
}
__device__ __forceinline__ void mma8(float* c, const uint32_t* a, const uint32_t* b) {
    asm volatile("mma.sync.aligned.m16n8k8.row.col.f32.tf32.tf32.f32 "
                 "{%0,%1,%2,%3}, {%4,%5,%6,%7}, {%8,%9}, {%0,%1,%2,%3};"
                 : "+f"(c[0]), "+f"(c[1]), "+f"(c[2]), "+f"(c[3])
                 : "r"(a[0]), "r"(a[1]), "r"(a[2]), "r"(a[3]), "r"(b[0]), "r"(b[1]));
}

// Per l: Y[o, n] = sum_i W[o,i] * X[n, i], n = (batch, dd). Persistent CTAs:
// each CTA owns one M-tile (128 of 256 output rows), keeps the tf32 W tile in
// SMEM for its whole life, and loops over batch tiles. CTA tile 128 x NT
// (NT = BT*D, padded to 256 in SMEM), K = 256 in 8 chunks of 32.
// 8 warps, 2(M) x 4(N) grid of 64x64 warp tiles, m16n8k8 tf32 mma.
template <int D, int BT>
__global__ __launch_bounds__(256, 1)
void so3_kernel(const float* __restrict__ x, const float* __restrict__ W,
                const float* __restrict__ bias, float* __restrict__ out,
                int off_l, int n_items)
{
    constexpr int NT = BT * D;       // <= 240, multiple of 8
    constexpr int H  = NT / 2;       // epilogue pass width (cols), multiple of 8
    constexpr int HB = BT / 2;       // batches per epilogue pass

    extern __shared__ char smem[];
    char*  As  = smem;
    char*  Bs  = smem + A_BYTES;
    float* epi = reinterpret_cast<float*>(smem + A_BYTES);   // reuses B region

    const int tid  = threadIdx.x;
    const int lane = tid & 31;
    const int wid  = tid >> 5;
    const int wm   = wid >> 2;       // 0..1
    const int wn   = wid & 3;        // 0..3
    const int mt   = blockIdx.x & 1;
    const int m0   = mt * 128;

    // ---- preload W tile (128 x 256) as tf32, SW128, split into 8 K-chunks ----
    for (int q = tid; q < 128 * 64; q += 256) {
        int r  = q >> 6;
        int cq = q & 63;
        float4 v = *reinterpret_cast<const float4*>(W + (size_t)(m0 + r) * 256 + cq * 4);
        uint4 u;
        u.x = f2tf32(v.x); u.y = f2tf32(v.y); u.z = f2tf32(v.z); u.w = f2tf32(v.w);
        *reinterpret_cast<uint4*>(As + (cq >> 3) * 16384 +
                                  sw128((uint32_t)(r * 128 + (cq & 7) * 16))) = u;
    }
    // ---- zero pad B rows [NT, 256) in both buffers (read by mma, never written) ----
    constexpr int PAD_Q = (B_ROWS - NT) * 8 * 2;
    for (int q = tid; q < PAD_Q; q += 256) {
        int b   = q / ((B_ROWS - NT) * 8);
        int r   = q % ((B_ROWS - NT) * 8);
        int row = NT + (r >> 3);
        int g   = r & 7;
        *reinterpret_cast<uint4*>(Bs + b * B_BUF + row * 128 + g * 16) =
            make_uint4(0, 0, 0, 0);
    }

    // ldmatrix lane address components
    const int a_row = wm * 64 + ((lane >> 3) & 1) * 8 + (lane & 7);
    const int a_col = ((lane >> 4) & 1) * 16;
    const int b_row = wn * 64 + ((lane >> 4) & 1) * 8 + (lane & 7);
    const int b_col = ((lane >> 3) & 1) * 16;
    const uint32_t As_u = smem_u32(smem);
    const uint32_t Bs_u = As_u + A_BYTES;

    float acc[4][8][4];

    for (int it = blockIdx.x; it < n_items; it += gridDim.x) {
        const int tile = it >> 1;
        const int b0   = tile * BT;

#pragma unroll
        for (int fm = 0; fm < 4; fm++)
#pragma unroll
            for (int fn = 0; fn < 8; fn++)
#pragma unroll
                for (int e = 0; e < 4; e++) acc[fm][fn][e] = 0.0f;

        // B chunk loader: contiguous 32*D floats per batch -> SW128 scatter (tf32)
        auto loadB = [&](int kc, int buf) {
            const float* src0 = x + off_l + kc * (32 * D);
            char* dst = Bs + buf * B_BUF;
            constexpr int F4 = NT * 8;
            for (int q = tid; q < F4; q += 256) {
                int j  = q * 4;
                int bb = j / (32 * D);
                int jj = j - bb * (32 * D);
                float e0 = 0.f, e1 = 0.f, e2 = 0.f, e3 = 0.f;
                if (b0 + bb < BATCH) {
                    float4 v = *reinterpret_cast<const float4*>(
                        src0 + (size_t)(b0 + bb) * 4096 + jj);
                    e0 = v.x; e1 = v.y; e2 = v.z; e3 = v.w;
                }
                float vv[4] = {e0, e1, e2, e3};
#pragma unroll
                for (int e = 0; e < 4; e++) {
                    int je = jj + e;
                    int i  = je / D;
                    int dd = je - i * D;
                    int n  = bb * D + dd;
                    *reinterpret_cast<uint32_t*>(
                        dst + sw128((uint32_t)(n * 128 + i * 4))) = f2tf32(vv[e]);
                }
            }
        };

        loadB(0, 0);
        __syncthreads();

#pragma unroll 1
        for (int kc = 0; kc < 8; kc++) {
            if (kc < 7) loadB(kc + 1, (kc + 1) & 1);
            const uint32_t Ac = As_u + kc * 16384;
            const uint32_t Bc = Bs_u + (kc & 1) * B_BUF;
#pragma unroll
            for (int ks = 0; ks < 4; ks++) {
                uint32_t af[4][4], bf[4][4];
#pragma unroll
                for (int fm = 0; fm < 4; fm++)
                    ldsm4(af[fm], Ac + sw128((uint32_t)((a_row + fm * 16) * 128 +
                                                        ks * 32 + a_col)));
#pragma unroll
                for (int g = 0; g < 4; g++)
                    ldsm4(bf[g], Bc + sw128((uint32_t)((b_row + g * 16) * 128 +
                                                       ks * 32 + b_col)));
#pragma unroll
                for (int fm = 0; fm < 4; fm++)
#pragma unroll
                    for (int g = 0; g < 4; g++) {
                        mma8(acc[fm][2 * g],     af[fm], &bf[g][0]);
                        mma8(acc[fm][2 * g + 1], af[fm], &bf[g][2]);
                    }
            }
            __syncthreads();
        }

        // ---- epilogue: two passes, staged through SMEM for coalesced stores ----
#pragma unroll 1
        for (int p = 0; p < 2; p++) {
#pragma unroll
            for (int fm = 0; fm < 4; fm++) {
                int m = wm * 64 + fm * 16 + (lane >> 2);
#pragma unroll
                for (int fn = 0; fn < 8; fn++) {
                    int nb = wn * 64 + fn * 8;
                    if (nb >= p * H && nb < p * H + H) {
                        const float* c = acc[fm][fn];
                        int n0  = nb - p * H + (lane & 3) * 2;
                        int bb0 = n0 / D, dd0 = n0 - bb0 * D;
                        int n1  = n0 + 1;
                        int bb1 = n1 / D, dd1 = n1 - bb1 * D;
                        epi[bb0 * (128 * D) + m * D + dd0]       = c[0];
                        epi[bb1 * (128 * D) + m * D + dd1]       = c[1];
                        epi[bb0 * (128 * D) + (m + 8) * D + dd0] = c[2];
                        epi[bb1 * (128 * D) + (m + 8) * D + dd1] = c[3];
                    }
                }
            }
            __syncthreads();

            const int base_b = b0 + p * HB;
            const float4* e4 = reinterpret_cast<const float4*>(epi);
            for (int q = tid; q < HB * 32 * D; q += 256) {
                int bb = q / (32 * D);
                int r  = q - bb * (32 * D);
                int gb = base_b + bb;
                if (gb < BATCH) {
                    float4 v = e4[(size_t)bb * 32 * D + r];
                    if (D == 1) {
                        float4 bv = *reinterpret_cast<const float4*>(bias + m0 + r * 4);
                        v.x += bv.x; v.y += bv.y; v.z += bv.z; v.w += bv.w;
                    }
                    *reinterpret_cast<float4*>(
                        out + (size_t)gb * 4096 + off_l + m0 * D + r * 4) = v;
                }
            }
            __syncthreads();
        }
    }
}

// ---------------- launch ----------------

extern "C" void kernel_launch(void* const* d_in, const int* in_sizes, int n_in,
                              void* d_out, int out_size) {
    const float* x    = (const float*)d_in[0];
    const float* W0   = (const float*)d_in[1];
    const float* W1   = (const float*)d_in[2];
    const float* W2   = (const float*)d_in[3];
    const float* W3   = (const float*)d_in[4];
    const float* bias = (const float*)d_in[5];
    float* out = (float*)d_out;

    cudaFuncSetAttribute(so3_kernel<1, 240>,
                         cudaFuncAttributeMaxDynamicSharedMemorySize, SMEM_BYTES);
    cudaFuncSetAttribute(so3_kernel<3, 80>,
                         cudaFuncAttributeMaxDynamicSharedMemorySize, SMEM_BYTES);
    cudaFuncSetAttribute(so3_kernel<5, 48>,
                         cudaFuncAttributeMaxDynamicSharedMemorySize, SMEM_BYTES);
    cudaFuncSetAttribute(so3_kernel<7, 32>,
                         cudaFuncAttributeMaxDynamicSharedMemorySize, SMEM_BYTES);

    const int GRID = 304;  // 2 * 152 SMs, even so each CTA keeps one fixed M-tile

    // items = 2 * ceil(BATCH / BT)
    so3_kernel<1, 240><<<GRID, 256, SMEM_BYTES>>>(x, W0, bias, out, 0,    2 * 84);
    so3_kernel<3, 80> <<<GRID, 256, SMEM_BYTES>>>(x, W1, bias, out, 256,  2 * 250);
    so3_kernel<5, 48> <<<GRID, 256, SMEM_BYTES>>>(x, W2, bias, out, 1024, 2 * 417);
    so3_kernel<7, 32> <<<GRID, 256, SMEM_BYTES>>>(x, W3, bias, out, 2304, 2 * 625);
}

// round 3
// speedup vs baseline: 2.0565x; 2.0565x over previous
#include <cuda_runtime.h>
#include <cstdint>

static constexpr int BATCH   = 20000;
static constexpr int A_BYTES = 131072;   // 8 K-chunks x 128 rows x 128B tf32 W tile

__device__ __forceinline__ uint32_t smem_u32(const void* p) {
    uint32_t a;
    asm("{ .reg .u64 t; cvta.to.shared.u64 t, %1; cvt.u32.u64 %0, t; }" : "=r"(a) : "l"(p));
    return a;
}
__device__ __forceinline__ uint32_t f2tf32(float f) {
    uint32_t u;
    asm("cvt.rna.tf32.f32 %0, %1;" : "=r"(u) : "f"(f));
    return u;
}
__device__ __forceinline__ uint32_t sw128(uint32_t o) { return o ^ ((o >> 3) & 0x70); }

__device__ __forceinline__ void ldsm4(uint32_t* r, uint32_t a) {
    asm volatile("ldmatrix.sync.aligned.m8n8.x4.shared.b16 {%0,%1,%2,%3}, [%4];"
                 : "=r"(r[0]), "=r"(r[1]), "=r"(r[2]), "=r"(r[3]) : "r"(a));
}
__device__ __forceinline__ void ldsm2(uint32_t* r, uint32_t a) {
    asm volatile("ldmatrix.sync.aligned.m8n8.x2.shared.b16 {%0,%1}, [%2];"
                 : "=r"(r[0]), "=r"(r[1]) : "r"(a));
}
__device__ __forceinline__ void mma8(float* c, const uint32_t* a, const uint32_t* b) {
    asm volatile("mma.sync.aligned.m16n8k8.row.col.f32.tf32.tf32.f32 "
                 "{%0,%1,%2,%3}, {%4,%5,%6,%7}, {%8,%9}, {%0,%1,%2,%3};"
                 : "+f"(c[0]), "+f"(c[1]), "+f"(c[2]), "+f"(c[3])
                 : "r"(a[0]), "r"(a[1]), "r"(a[2]), "r"(a[3]), "r"(b[0]), "r"(b[1]));
}

// Per l: Y[o, n] = sum_i W[o,i] * X[n, i], n = (batch, dd). Persistent CTA owns
// one M-tile (128 rows), keeps tf32 W in SMEM, loops over batch tiles.
// CTA tile 128 x NT (NT = BT*D), K = 256 in 8 chunks of 32, B double-buffered.
// 16 warps: 4(M,32 rows) x 4(N, NT/4 cols). LDGs for chunk kc+1 are held in
// registers across the chunk-kc MMA block, then converted+scattered to SMEM.
template <int D, int BT>
__global__ __launch_bounds__(512, 1)
void so3_kernel(const float* __restrict__ x, const float* __restrict__ W,
                const float* __restrict__ bias, float* __restrict__ out,
                int off_l, int n_items)
{
    constexpr int NT  = BT * D;          // multiple of 32, <= 224
    constexpr int WN  = NT / 4;          // warp n-tile (multiple of 8)
    constexpr int NF  = WN / 8;          // n8 fragments per warp
    constexpr int H   = NT / 2;          // epilogue half width
    constexpr int HB  = BT / 2;          // batches per epilogue pass
    constexpr int BSZ = NT * 128;        // bytes per B buffer
    constexpr int F4  = NT * 8;          // float4 loads per chunk

    extern __shared__ char smem[];
    char*  As  = smem;
    char*  Bs  = smem + A_BYTES;
    float* epi = reinterpret_cast<float*>(smem + A_BYTES);  // reuses B region

    const int tid  = threadIdx.x;
    const int lane = tid & 31;
    const int wid  = tid >> 5;
    const int wm   = wid >> 2;           // 0..3 -> m rows wm*32
    const int wn   = wid & 3;            // 0..3 -> n cols wn*WN
    const int m0   = (blockIdx.x & 1) * 128;

    // ---- preload W tile (128 x 256) as tf32, SW128, 8 K-chunk sub-tiles ----
    for (int q = tid; q < 128 * 64; q += 512) {
        int r  = q >> 6;
        int cq = q & 63;
        float4 v = *reinterpret_cast<const float4*>(W + (size_t)(m0 + r) * 256 + cq * 4);
        uint4 u;
        u.x = f2tf32(v.x); u.y = f2tf32(v.y); u.z = f2tf32(v.z); u.w = f2tf32(v.w);
        *reinterpret_cast<uint4*>(As + (cq >> 3) * 16384 +
                                  sw128((uint32_t)(r * 128 + (cq & 7) * 16))) = u;
    }

    // ldmatrix lane address components
    const int a_rowb = wm * 32 + ((lane >> 3) & 1) * 8 + (lane & 7);
    const int a_col  = ((lane >> 4) & 1) * 16;
    const int b_rowb = wn * WN + ((lane >> 4) & 1) * 8 + (lane & 7);
    const int b_col  = ((lane >> 3) & 1) * 16;
    const int b2_row = wn * WN + (NF - 1) * 8 + (lane & 7);
    const int b2_col = ((lane >> 3) & 1) * 16;
    const uint32_t As_u = smem_u32(smem);
    const uint32_t Bs_u = As_u + A_BYTES;

    float acc[2][NF][4];
    float4 hold[4];

    for (int it = blockIdx.x; it < n_items; it += gridDim.x) {
        const int b0 = (it >> 1) * BT;

#pragma unroll
        for (int fm = 0; fm < 2; fm++)
#pragma unroll
            for (int fn = 0; fn < NF; fn++)
#pragma unroll
                for (int e = 0; e < 4; e++) acc[fm][fn][e] = 0.0f;

        // issue LDGs for chunk kc into hold[] (no smem writes)
        auto ldgB = [&](int kc) {
            const float* src0 = x + off_l + kc * (32 * D);
#pragma unroll
            for (int h = 0; h < 4; h++) {
                int q = tid + h * 512;
                hold[h] = make_float4(0.f, 0.f, 0.f, 0.f);
                if (q < F4) {
                    int j  = q * 4;
                    int bb = j / (32 * D);
                    int jj = j - bb * (32 * D);
                    if (b0 + bb < BATCH)
                        hold[h] = *reinterpret_cast<const float4*>(
                            src0 + (size_t)(b0 + bb) * 4096 + jj);
                }
            }
        };
        // convert + scatter hold[] into B buffer (SW128 rows: n x 32 k-floats)
        auto stsB = [&](int buf) {
            char* dst = Bs + buf * BSZ;
#pragma unroll
            for (int h = 0; h < 4; h++) {
                int q = tid + h * 512;
                if (q < F4) {
                    int j  = q * 4;
                    int bb = j / (32 * D);
                    int jj = j - bb * (32 * D);
                    float vv[4] = {hold[h].x, hold[h].y, hold[h].z, hold[h].w};
#pragma unroll
                    for (int e = 0; e < 4; e++) {
                        int je = jj + e;
                        int i  = je / D;
                        int dd = je - i * D;
                        int n  = bb * D + dd;
                        *reinterpret_cast<uint32_t*>(
                            dst + sw128((uint32_t)(n * 128 + i * 4))) = f2tf32(vv[e]);
                    }
                }
            }
        };

        ldgB(0);
        stsB(0);
        __syncthreads();

#pragma unroll 1
        for (int kc = 0; kc < 8; kc++) {
            if (kc < 7) ldgB(kc + 1);
            const uint32_t Ac = As_u + kc * 16384;
            const uint32_t Bc = Bs_u + (kc & 1) * BSZ;
#pragma unroll
            for (int ks = 0; ks < 4; ks++) {
                uint32_t af[2][4];
#pragma unroll
                for (int fm = 0; fm < 2; fm++)
                    ldsm4(af[fm], Ac + sw128((uint32_t)((a_rowb + fm * 16) * 128 +
                                                        ks * 32 + a_col)));
                uint32_t bfr[NF][2];
#pragma unroll
                for (int g = 0; g < NF / 2; g++) {
                    uint32_t t[4];
                    ldsm4(t, Bc + sw128((uint32_t)((b_rowb + g * 16) * 128 +
                                                   ks * 32 + b_col)));
                    bfr[2 * g][0] = t[0]; bfr[2 * g][1] = t[1];
                    bfr[2 * g + 1][0] = t[2]; bfr[2 * g + 1][1] = t[3];
                }
                if (NF & 1) {
                    ldsm2(bfr[NF - 1], Bc + sw128((uint32_t)(b2_row * 128 +
                                                             ks * 32 + b2_col)));
                }
#pragma unroll
                for (int fm = 0; fm < 2; fm++)
#pragma unroll
                    for (int fn = 0; fn < NF; fn++)
                        mma8(acc[fm][fn], af[fm], bfr[fn]);
            }
            if (kc < 7) stsB((kc + 1) & 1);
            __syncthreads();
        }

        // ---- epilogue: 2 passes staged through SMEM for coalesced stores ----
#pragma unroll 1
        for (int p = 0; p < 2; p++) {
            if ((wn >> 1) == p) {
#pragma unroll
                for (int fm = 0; fm < 2; fm++) {
                    int m = wm * 32 + fm * 16 + (lane >> 2);
#pragma unroll
                    for (int fn = 0; fn < NF; fn++) {
                        const float* c = acc[fm][fn];
                        int n0  = (wn & 1) * WN + fn * 8 + (lane & 3) * 2;
                        int n1  = n0 + 1;
                        int bb0 = n0 / D, dd0 = n0 - bb0 * D;
                        int bb1 = n1 / D, dd1 = n1 - bb1 * D;
                        epi[bb0 * (128 * D) + m * D + dd0]       = c[0];
                        epi[bb1 * (128 * D) + m * D + dd1]       = c[1];
                        epi[bb0 * (128 * D) + (m + 8) * D + dd0] = c[2];
                        epi[bb1 * (128 * D) + (m + 8) * D + dd1] = c[3];
                    }
                }
            }
            __syncthreads();

            const int base_b = b0 + p * HB;
            const float4* e4 = reinterpret_cast<const float4*>(epi);
            for (int q = tid; q < HB * 32 * D; q += 512) {
                int bb = q / (32 * D);
                int r  = q - bb * (32 * D);
                int gb = base_b + bb;
                if (gb < BATCH) {
                    float4 v = e4[(size_t)bb * 32 * D + r];
                    if (D == 1) {
                        float4 bv = *reinterpret_cast<const float4*>(bias + m0 + r * 4);
                        v.x += bv.x; v.y += bv.y; v.z += bv.z; v.w += bv.w;
                    }
                    *reinterpret_cast<float4*>(
                        out + (size_t)gb * 4096 + off_l + m0 * D + r * 4) = v;
                }
            }
            __syncthreads();
        }
    }
}

// ---------------- launch ----------------

extern "C" void kernel_launch(void* const* d_in, const int* in_sizes, int n_in,
                              void* d_out, int out_size) {
    const float* x    = (const float*)d_in[0];
    const float* W0   = (const float*)d_in[1];
    const float* W1   = (const float*)d_in[2];
    const float* W2   = (const float*)d_in[3];
    const float* W3   = (const float*)d_in[4];
    const float* bias = (const float*)d_in[5];
    float* out = (float*)d_out;

    // smem = 128KB W tile + 2 B buffers (NT*128 each)
    cudaFuncSetAttribute(so3_kernel<1, 224>,
                         cudaFuncAttributeMaxDynamicSharedMemorySize, A_BYTES + 2 * 224 * 128);
    cudaFuncSetAttribute(so3_kernel<3, 64>,
                         cudaFuncAttributeMaxDynamicSharedMemorySize, A_BYTES + 2 * 192 * 128);
    cudaFuncSetAttribute(so3_kernel<5, 32>,
                         cudaFuncAttributeMaxDynamicSharedMemorySize, A_BYTES + 2 * 160 * 128);
    cudaFuncSetAttribute(so3_kernel<7, 32>,
                         cudaFuncAttributeMaxDynamicSharedMemorySize, A_BYTES + 2 * 224 * 128);

    const int GRID = 304;  // even: each CTA keeps a fixed M-tile (blockIdx & 1)

    // n_items = 2 * ceil(BATCH / BT)
    so3_kernel<1, 224><<<GRID, 512, A_BYTES + 2 * 224 * 128>>>(x, W0, bias, out, 0,    2 * 90);
    so3_kernel<3, 64> <<<GRID, 512, A_BYTES + 2 * 192 * 128>>>(x, W1, bias, out, 256,  2 * 313);
    so3_kernel<5, 32> <<<GRID, 512, A_BYTES + 2 * 160 * 128>>>(x, W2, bias, out, 1024, 2 * 625);
    so3_kernel<7, 32> <<<GRID, 512, A_BYTES + 2 * 224 * 128>>>(x, W3, bias, out, 2304, 2 * 625);
}

// round 4
// speedup vs baseline: 2.3217x; 1.1289x over previous
#include <cuda_runtime.h>
#include <cstdint>

static constexpr int BATCH   = 20000;
static constexpr int A_BYTES = 131072;   // 8 K-chunks x 128 rows x 128B tf32 W tile
static constexpr int GRID    = 152;      // one persistent CTA per SM
static constexpr int SMEM_BYTES = A_BYTES + 2 * 224 * 128;   // max NT = 224

__device__ __forceinline__ uint32_t smem_u32(const void* p) {
    uint32_t a;
    asm("{ .reg .u64 t; cvta.to.shared.u64 t, %1; cvt.u32.u64 %0, t; }" : "=r"(a) : "l"(p));
    return a;
}
__device__ __forceinline__ uint32_t f2tf32(float f) {
    uint32_t u;
    asm("cvt.rna.tf32.f32 %0, %1;" : "=r"(u) : "f"(f));
    return u;
}
__device__ __forceinline__ uint32_t sw128(uint32_t o) { return o ^ ((o >> 3) & 0x70); }

__device__ __forceinline__ void ldsm4(uint32_t* r, uint32_t a) {
    asm volatile("ldmatrix.sync.aligned.m8n8.x4.shared.b16 {%0,%1,%2,%3}, [%4];"
                 : "=r"(r[0]), "=r"(r[1]), "=r"(r[2]), "=r"(r[3]) : "r"(a));
}
__device__ __forceinline__ void ldsm2(uint32_t* r, uint32_t a) {
    asm volatile("ldmatrix.sync.aligned.m8n8.x2.shared.b16 {%0,%1}, [%2];"
                 : "=r"(r[0]), "=r"(r[1]) : "r"(a));
}
__device__ __forceinline__ void mma8(float* c, const uint32_t* a, const uint32_t* b) {
    asm volatile("mma.sync.aligned.m16n8k8.row.col.f32.tf32.tf32.f32 "
                 "{%0,%1,%2,%3}, {%4,%5,%6,%7}, {%8,%9}, {%0,%1,%2,%3};"
                 : "+f"(c[0]), "+f"(c[1]), "+f"(c[2]), "+f"(c[3])
                 : "r"(a[0]), "r"(a[1]), "r"(a[2]), "r"(a[3]), "r"(b[0]), "r"(b[1]));
}

// Per l: Y[o, n] = sum_i W[o,i] * X[n, i], n = (batch, dd). One persistent CTA
// per SM walks a flat item list covering all four l's (item = l-base + tile*2 + mt).
// Since GRID and all range bases are even, each CTA keeps one M-tile parity for
// its whole life, so the 128KB tf32 W tile is (re)loaded only on l-range entry.
// CTA tile 128 x NT, K=256 in 8 chunks of 32, B double-buffered through SMEM.
// 16 warps as 4(M)x4(N); next chunk's LDGs held in regs across the MMA block;
// next tile's chunk-0 LDGs held across the epilogue.
template <int D, int BT>
__device__ __forceinline__ void run_range(
    const float* __restrict__ x, const float* __restrict__ W,
    const float* __restrict__ bias, float* __restrict__ out,
    int off_l, int lo, int hi)
{
    constexpr int NT  = BT * D;          // multiple of 32, <= 224
    constexpr int WN  = NT / 4;          // warp n-tile
    constexpr int NF  = WN / 8;          // n8 fragments per warp
    constexpr int HB  = BT / 2;          // batches per epilogue pass
    constexpr int BSZ = NT * 128;        // bytes per B buffer
    constexpr int F4  = NT * 8;          // float4 loads per chunk

    const int cta = blockIdx.x;
    int rr = (cta - lo) % GRID; if (rr < 0) rr += GRID;
    const int start = lo + rr;
    if (start >= hi) return;             // uniform per CTA — no divergent syncs

    extern __shared__ char smem[];
    char*  As  = smem;
    char*  Bs  = smem + A_BYTES;
    float* epi = reinterpret_cast<float*>(Bs);   // epilogue reuses B region

    const int tid  = threadIdx.x;
    const int lane = tid & 31;
    const int wid  = tid >> 5;
    const int wm   = wid >> 2;
    const int wn   = wid & 3;
    const int m0   = (cta & 1) * 128;    // constant M-tile parity per CTA

    __syncthreads();   // previous range fully done with SMEM
    // ---- preload W tile (128 x 256) as tf32, SW128, 8 K-chunk sub-tiles ----
    for (int q = tid; q < 128 * 64; q += 512) {
        int r  = q >> 6;
        int cq = q & 63;
        float4 v = *reinterpret_cast<const float4*>(W + (size_t)(m0 + r) * 256 + cq * 4);
        uint4 u;
        u.x = f2tf32(v.x); u.y = f2tf32(v.y); u.z = f2tf32(v.z); u.w = f2tf32(v.w);
        *reinterpret_cast<uint4*>(As + (cq >> 3) * 16384 +
                                  sw128((uint32_t)(r * 128 + (cq & 7) * 16))) = u;
    }

    const int a_rowb = wm * 32 + ((lane >> 3) & 1) * 8 + (lane & 7);
    const int a_col  = ((lane >> 4) & 1) * 16;
    const int b_rowb = wn * WN + ((lane >> 4) & 1) * 8 + (lane & 7);
    const int b_col  = ((lane >> 3) & 1) * 16;
    const int b2_row = wn * WN + (NF - 1) * 8 + (lane & 7);
    const uint32_t As_u = smem_u32(smem);
    const uint32_t Bs_u = As_u + A_BYTES;

    float acc[2][NF][4];
    float4 hold[4];

    // issue LDGs for (batch-tile b0, chunk kc) into hold[] — no smem writes
    auto ldgB = [&](int b0, int kc) {
        const float* src0 = x + off_l + kc * (32 * D);
#pragma unroll
        for (int h = 0; h < 4; h++) {
            int q = tid + h * 512;
            hold[h] = make_float4(0.f, 0.f, 0.f, 0.f);
            if (q < F4) {
                int j  = q * 4;
                int bb = j / (32 * D);
                int jj = j - bb * (32 * D);
                if (b0 + bb < BATCH)
                    hold[h] = *reinterpret_cast<const float4*>(
                        src0 + (size_t)(b0 + bb) * 4096 + jj);
            }
        }
    };
    // convert + scatter hold[] into B buffer (SW128 rows: n x 32 k-floats)
    auto stsB = [&](int buf) {
        char* dst = Bs + buf * BSZ;
#pragma unroll
        for (int h = 0; h < 4; h++) {
            int q = tid + h * 512;
            if (q < F4) {
                int j  = q * 4;
                int bb = j / (32 * D);
                int jj = j - bb * (32 * D);
                float vv[4] = {hold[h].x, hold[h].y, hold[h].z, hold[h].w};
#pragma unroll
                for (int e = 0; e < 4; e++) {
                    int je = jj + e;
                    int i  = je / D;
                    int dd = je - i * D;
                    int n  = bb * D + dd;
                    *reinterpret_cast<uint32_t*>(
                        dst + sw128((uint32_t)(n * 128 + i * 4))) = f2tf32(vv[e]);
                }
            }
        }
    };

    ldgB(((start - lo) >> 1) * BT, 0);   // first tile, chunk 0

    for (int it = start; it < hi; it += GRID) {
        const int b0 = ((it - lo) >> 1) * BT;

#pragma unroll
        for (int fm = 0; fm < 2; fm++)
#pragma unroll
            for (int fn = 0; fn < NF; fn++)
#pragma unroll
                for (int e = 0; e < 4; e++) acc[fm][fn][e] = 0.0f;

        stsB(0);          // chunk 0 (holds loaded pre-loop / during prev chunk 7)
        __syncthreads();  // also covers W-tile publication on first iteration

#pragma unroll 1
        for (int kc = 0; kc < 8; kc++) {
            if (kc < 7) ldgB(b0, kc + 1);
            else if (it + GRID < hi) ldgB(((it + GRID - lo) >> 1) * BT, 0);
            const uint32_t Ac = As_u + kc * 16384;
            const uint32_t Bc = Bs_u + (kc & 1) * BSZ;
#pragma unroll
            for (int ks = 0; ks < 4; ks++) {
                uint32_t af[2][4];
#pragma unroll
                for (int fm = 0; fm < 2; fm++)
                    ldsm4(af[fm], Ac + sw128((uint32_t)((a_rowb + fm * 16) * 128 +
                                                        ks * 32 + a_col)));
                uint32_t bfr[NF][2];
#pragma unroll
                for (int g = 0; g < NF / 2; g++) {
                    uint32_t t[4];
                    ldsm4(t, Bc + sw128((uint32_t)((b_rowb + g * 16) * 128 +
                                                   ks * 32 + b_col)));
                    bfr[2 * g][0] = t[0]; bfr[2 * g][1] = t[1];
                    bfr[2 * g + 1][0] = t[2]; bfr[2 * g + 1][1] = t[3];
                }
                if (NF & 1) {
                    ldsm2(bfr[NF - 1], Bc + sw128((uint32_t)(b2_row * 128 +
                                                             ks * 32 + b_col)));
                }
#pragma unroll
                for (int fm = 0; fm < 2; fm++)
#pragma unroll
                    for (int fn = 0; fn < NF; fn++)
                        mma8(acc[fm][fn], af[fm], bfr[fn]);
            }
            if (kc < 7) stsB((kc + 1) & 1);
            __syncthreads();
        }

        // ---- epilogue: 2 passes staged through SMEM for coalesced stores ----
#pragma unroll 1
        for (int p = 0; p < 2; p++) {
            if ((wn >> 1) == p) {
#pragma unroll
                for (int fm = 0; fm < 2; fm++) {
                    int m = wm * 32 + fm * 16 + (lane >> 2);
#pragma unroll
                    for (int fn = 0; fn < NF; fn++) {
                        const float* c = acc[fm][fn];
                        int n0  = (wn & 1) * WN + fn * 8 + (lane & 3) * 2;
                        int n1  = n0 + 1;
                        int bb0 = n0 / D, dd0 = n0 - bb0 * D;
                        int bb1 = n1 / D, dd1 = n1 - bb1 * D;
                        epi[bb0 * (128 * D) + m * D + dd0]       = c[0];
                        epi[bb1 * (128 * D) + m * D + dd1]       = c[1];
                        epi[bb0 * (128 * D) + (m + 8) * D + dd0] = c[2];
                        epi[bb1 * (128 * D) + (m + 8) * D + dd1] = c[3];
                    }
                }
            }
            __syncthreads();

            const int base_b = b0 + p * HB;
            const float4* e4 = reinterpret_cast<const float4*>(epi);
            for (int q = tid; q < HB * 32 * D; q += 512) {
                int bb = q / (32 * D);
                int r  = q - bb * (32 * D);
                int gb = base_b + bb;
                if (gb < BATCH) {
                    float4 v = e4[(size_t)bb * 32 * D + r];
                    if (D == 1) {
                        float4 bv = *reinterpret_cast<const float4*>(bias + m0 + r * 4);
                        v.x += bv.x; v.y += bv.y; v.z += bv.z; v.w += bv.w;
                    }
                    *reinterpret_cast<float4*>(
                        out + (size_t)gb * 4096 + off_l + m0 * D + r * 4) = v;
                }
            }
            __syncthreads();
        }
    }
}

// Flat item ranges (all bases even; items = 2 * n_tiles):
//  l0: D=1, BT=224, 90 tiles  -> [   0,  180)
//  l1: D=3, BT=64, 313 tiles  -> [ 180,  806)
//  l2: D=5, BT=32, 625 tiles  -> [ 806, 2056)
//  l3: D=7, BT=32, 625 tiles  -> [2056, 3306)
__global__ __launch_bounds__(512, 1)
void so3_fused(const float* __restrict__ x,
               const float* __restrict__ W0, const float* __restrict__ W1,
               const float* __restrict__ W2, const float* __restrict__ W3,
               const float* __restrict__ bias, float* __restrict__ out)
{
    run_range<1, 224>(x, W0, bias, out, 0,       0,  180);
    run_range<3,  64>(x, W1, bias, out, 256,   180,  806);
    run_range<5,  32>(x, W2, bias, out, 1024,  806, 2056);
    run_range<7,  32>(x, W3, bias, out, 2304, 2056, 3306);
}

extern "C" void kernel_launch(void* const* d_in, const int* in_sizes, int n_in,
                              void* d_out, int out_size) {
    const float* x    = (const float*)d_in[0];
    const float* W0   = (const float*)d_in[1];
    const float* W1   = (const float*)d_in[2];
    const float* W2   = (const float*)d_in[3];
    const float* W3   = (const float*)d_in[4];
    const float* bias = (const float*)d_in[5];
    float* out = (float*)d_out;

    cudaFuncSetAttribute(so3_fused, cudaFuncAttributeMaxDynamicSharedMemorySize,
                         SMEM_BYTES);
    so3_fused<<<GRID, 512, SMEM_BYTES>>>(x, W0, W1, W2, W3, bias, out);
}